// round 5
// baseline (speedup 1.0000x reference)
#include <cuda_runtime.h>
#include <cuda_fp16.h>
#include <cstdint>
#include <cstddef>

// ---------------------------------------------------------------------------
// FastKAN layer as ONE fp16 GEMM (mma.sync path; tcgen05 unavailable: harness
// compiles PTX at compute_103 which lacks the "a"-suffix features):
//   out[b,j] = sum_{i,s} A[b, i*36+s] * B[j, i*36+s]
//   s in [0,35): cubic B-spline basis coeff c=s;  s==35: silu(x_norm) slot,
//   with B[j, i*36+35] = base_scale[i,j].
// Round 5: merged prep kernel; GEMM ks-level software pipelining (double-
// buffered fragments, LDSM ahead of HMMA); B fragments via ldmatrix.x4.
// ---------------------------------------------------------------------------

#define BATCH   4096
#define INDIM   1024
#define OUTDIM  1024
#define NC      35
#define SLOTS   36
#define KTOT    (INDIM * SLOTS)      // 36864

#define BM      256
#define BN      128
#define BK      64                   // fp16 per K-chunk (128B rows)
#define STAGES  4
#define ITERS   (KTOT / BK)          // 576
#define ATILEB  (BM * BK * 2)        // 32768 bytes
#define BTILEB  (BN * BK * 2)        // 16384 bytes
#define STGB    (ATILEB + BTILEB)    // 49152
#define SMEM_TOTAL (STAGES * STGB)   // 196608

#define NBLK_B  (KTOT / 256 * (OUTDIM / 4))   // 144*256 = 36864 blocks
#define NBLK_A  ((BATCH * INDIM) / 256)       // 16384 blocks

__device__ __align__(128) __half g_A[(size_t)BATCH  * KTOT];  // ~302 MB
__device__ __align__(128) __half g_B[(size_t)OUTDIM * KTOT];  //  ~74 MB

// ------------------------------- helpers -----------------------------------
__device__ __forceinline__ uint32_t smem_u32(const void* p) {
    uint32_t a;
    asm("{ .reg .u64 t; cvta.to.shared.u64 t, %1; cvt.u32.u64 %0, t; }" : "=r"(a) : "l"(p));
    return a;
}
__device__ __forceinline__ void cp16(uint32_t s, const void* g) {
    asm volatile("cp.async.cg.shared.global [%0], [%1], 16;" :: "r"(s), "l"(g) : "memory");
}
#define CP_COMMIT() asm volatile("cp.async.commit_group;" ::: "memory")
#define CP_WAIT(n)  asm volatile("cp.async.wait_group %0;" :: "n"(n) : "memory")
#define SWZ(off) ((off) ^ (((off) >> 3) & 0x70))

// ---------------------------------------------------------------------------
// prep: one kernel, two regions.
//  blocks [0, NBLK_B): pack spline_weight + base_scale -> g_B[j][i*36+s]
//  blocks [NBLK_B, NBLK_B+NBLK_A): basis(x) + silu -> g_A[b][i*36+s]
// ---------------------------------------------------------------------------
__global__ void prep(const float* __restrict__ x, const float* __restrict__ grid,
                     const float* __restrict__ W, const float* __restrict__ bs) {
    int bx  = blockIdx.x;
    int tid = threadIdx.x;

    if (bx < NBLK_B) {
        int kk = (bx % (KTOT / 256)) * 256 + tid;   // [0, 36864)
        int j0 = (bx / (KTOT / 256)) * 4;
        int i  = kk / SLOTS;
        int s  = kk - i * SLOTS;
        #pragma unroll
        for (int q = 0; q < 4; q++) {
            int j = j0 + q;
            float v = (s < NC) ? W[((size_t)i * OUTDIM + j) * NC + s]
                               : bs[(size_t)i * OUTDIM + j];
            g_B[(size_t)j * KTOT + kk] = __float2half_rn(v);
        }
        return;
    }

    // ---- prep_A region ----
    __shared__ __half sbuf[256 * SLOTS];
    int ab = bx - NBLK_B;
    size_t pair0 = (size_t)ab * 256;
    float xv = x[pair0 + tid];
    float xn = fminf(fmaxf(xv, -0.99f), 0.99f);

    half2* my2 = (half2*)(sbuf + tid * SLOTS);   // 36 halves = 72B, 4B-aligned
    #pragma unroll
    for (int q = 0; q < SLOTS / 2; q++) my2[q] = __floats2half2_rn(0.f, 0.f);
    __half* my = sbuf + tid * SLOTS;

    const float invh = 17.0f;                     // (NC-1)/2
    float t = (xn + 1.0f) * invh;
    int cl = (int)floorf(t) - 1;                  // active c in [cl, cl+3]
    #pragma unroll
    for (int q = 0; q < 4; q++) {
        int c = cl + q;
        if (c >= 0 && c < NC) {
            float d = fabsf(xn - grid[c]) * invh;
            float inner = 0.66666667f - d * d + d * d * d * 0.5f;
            float tt = 2.0f - d;
            float outer = tt * tt * tt * (1.0f / 6.0f);
            float v = (d < 1.0f) ? inner : ((d < 2.0f) ? outer : 0.0f);
            my[c] = __float2half_rn(v);
        }
    }
    my[NC] = __float2half_rn(xn / (1.0f + __expf(-xn)));
    __syncthreads();

    const uint32_t* s4 = (const uint32_t*)sbuf;
    uint32_t* g4 = (uint32_t*)(g_A + pair0 * SLOTS);
    #pragma unroll
    for (int w = 0; w < 4608 / 256; w++) g4[w * 256 + tid] = s4[w * 256 + tid];
}

// ---------------------------------------------------------------------------
// kan_gemm: 256x128 CTA tile, 4-stage cp.async + mma.sync m16n8k16.
// 8 warps as 4(M) x 2(N); warp tile 64x64. One wave: 128 CTAs.
// ks-level software pipelining with double-buffered fragments.
// ---------------------------------------------------------------------------
__global__ void __launch_bounds__(256, 1) kan_gemm(float* __restrict__ out) {
    extern __shared__ __align__(1024) char smem[];
    uint32_t sb = smem_u32(smem);
    int tid = threadIdx.x;
    int wid = tid >> 5;
    int lid = tid & 31;
    int tn  = blockIdx.x;       // [0,8)
    int tm  = blockIdx.y;       // [0,16)
    int wm  = wid & 3;          // 4 warps along M
    int wn  = wid >> 2;         // 2 warps along N

    const __half* gA = g_A + (size_t)(tm * BM) * KTOT;
    const __half* gB = g_B + (size_t)(tn * BN) * KTOT;

    // per-thread copy coordinates: A = 8 chunks of 16B, B = 4 chunks
    int arow[8]; uint32_t acol[8], adst[8];
    #pragma unroll
    for (int q = 0; q < 8; q++) {
        int ci = tid + q * 256;
        arow[q] = ci >> 3;
        acol[q] = (ci & 7) * 8;
        uint32_t off = (uint32_t)arow[q] * 128 + (ci & 7) * 16;
        adst[q] = SWZ(off);
    }
    int brow[4]; uint32_t bcol[4], bdst[4];
    #pragma unroll
    for (int q = 0; q < 4; q++) {
        int ci = tid + q * 256;
        brow[q] = ci >> 3;
        bcol[q] = (ci & 7) * 8;
        uint32_t off = (uint32_t)brow[q] * 128 + (ci & 7) * 16;
        bdst[q] = SWZ(off);
    }

    // precomputed (unswizzled) fragment base offsets
    // A tile mt: row = wm*64 + mt*16 + (lid&15); byte col = (lid>>4)*16
    uint32_t afoff[4];
    #pragma unroll
    for (int mt = 0; mt < 4; mt++) {
        uint32_t row = wm * 64 + mt * 16 + (lid & 15);
        afoff[mt] = row * 128 + (lid >> 4) * 16;
    }
    // B pair p (nt = 2p + (lid>>4 ... )): lanes 0-7 -> (nt0,h0), 8-15 -> (nt0,h1),
    // 16-23 -> (nt1,h0), 24-31 -> (nt1,h1)
    uint32_t bfoff[4];
    #pragma unroll
    for (int p = 0; p < 4; p++) {
        int g   = lid >> 3;              // 0..3
        int ntl = 2 * p + (g >> 1);
        int h   = g & 1;
        uint32_t row = wn * 64 + ntl * 8 + (lid & 7);
        bfoff[p] = row * 128 + h * 16;
    }

    float acc[4][8][4];
    #pragma unroll
    for (int a = 0; a < 4; a++)
        #pragma unroll
        for (int b = 0; b < 8; b++)
            #pragma unroll
            for (int c = 0; c < 4; c++) acc[a][b][c] = 0.f;

    auto copy_stage = [&](int it) {
        int s = it & (STAGES - 1);
        uint32_t sa  = sb + s * STGB;
        uint32_t sbm = sa + ATILEB;
        size_t k0 = (size_t)it * BK;
        #pragma unroll
        for (int q = 0; q < 8; q++)
            cp16(sa + adst[q], gA + (size_t)arow[q] * KTOT + k0 + acol[q]);
        #pragma unroll
        for (int q = 0; q < 4; q++)
            cp16(sbm + bdst[q], gB + (size_t)brow[q] * KTOT + k0 + bcol[q]);
        CP_COMMIT();
    };

    copy_stage(0); copy_stage(1); copy_stage(2);

    uint32_t af[2][4][4];
    uint32_t bf[2][4][4];

    auto load_frags = [&](int buf, uint32_t sa, uint32_t sbm, int ks) {
        uint32_t kb = (uint32_t)ks * 32;
        #pragma unroll
        for (int mt = 0; mt < 4; mt++) {
            uint32_t off = afoff[mt] + kb;
            uint32_t addr = sa + SWZ(off);
            asm volatile(
                "ldmatrix.sync.aligned.m8n8.x4.shared.b16 {%0,%1,%2,%3}, [%4];"
                : "=r"(af[buf][mt][0]), "=r"(af[buf][mt][1]),
                  "=r"(af[buf][mt][2]), "=r"(af[buf][mt][3])
                : "r"(addr));
        }
        #pragma unroll
        for (int p = 0; p < 4; p++) {
            uint32_t off = bfoff[p] + kb;
            uint32_t addr = sbm + SWZ(off);
            asm volatile(
                "ldmatrix.sync.aligned.m8n8.x4.shared.b16 {%0,%1,%2,%3}, [%4];"
                : "=r"(bf[buf][p][0]), "=r"(bf[buf][p][1]),
                  "=r"(bf[buf][p][2]), "=r"(bf[buf][p][3])
                : "r"(addr));
        }
    };

    for (int k = 0; k < ITERS; k++) {
        CP_WAIT(2);
        __syncthreads();
        if (k + 3 < ITERS) copy_stage(k + 3); else CP_COMMIT();

        uint32_t sa  = sb + (k & (STAGES - 1)) * STGB;
        uint32_t sbm = sa + ATILEB;

        load_frags(0, sa, sbm, 0);
        #pragma unroll
        for (int ks = 0; ks < 4; ks++) {
            int cur = ks & 1;
            if (ks < 3) load_frags(cur ^ 1, sa, sbm, ks + 1);
            #pragma unroll
            for (int mt = 0; mt < 4; mt++)
                #pragma unroll
                for (int p = 0; p < 4; p++) {
                    asm volatile(
                        "mma.sync.aligned.m16n8k16.row.col.f32.f16.f16.f32 "
                        "{%0,%1,%2,%3}, {%4,%5,%6,%7}, {%8,%9}, {%0,%1,%2,%3};"
                        : "+f"(acc[mt][2*p][0]), "+f"(acc[mt][2*p][1]),
                          "+f"(acc[mt][2*p][2]), "+f"(acc[mt][2*p][3])
                        : "r"(af[cur][mt][0]), "r"(af[cur][mt][1]),
                          "r"(af[cur][mt][2]), "r"(af[cur][mt][3]),
                          "r"(bf[cur][p][0]), "r"(bf[cur][p][1]));
                    asm volatile(
                        "mma.sync.aligned.m16n8k16.row.col.f32.f16.f16.f32 "
                        "{%0,%1,%2,%3}, {%4,%5,%6,%7}, {%8,%9}, {%0,%1,%2,%3};"
                        : "+f"(acc[mt][2*p+1][0]), "+f"(acc[mt][2*p+1][1]),
                          "+f"(acc[mt][2*p+1][2]), "+f"(acc[mt][2*p+1][3])
                        : "r"(af[cur][mt][0]), "r"(af[cur][mt][1]),
                          "r"(af[cur][mt][2]), "r"(af[cur][mt][3]),
                          "r"(bf[cur][p][2]), "r"(bf[cur][p][3]));
                }
        }
    }
    CP_WAIT(0);

    // Epilogue: mma accum layout -> gmem
    #pragma unroll
    for (int mt = 0; mt < 4; mt++) {
        int r0 = tm * BM + wm * 64 + mt * 16 + (lid >> 2);
        #pragma unroll
        for (int nt = 0; nt < 8; nt++) {
            int c0 = tn * BN + wn * 64 + nt * 8 + (lid & 3) * 2;
            *(float2*)(out + (size_t)r0 * OUTDIM + c0) =
                make_float2(acc[mt][nt][0], acc[mt][nt][1]);
            *(float2*)(out + (size_t)(r0 + 8) * OUTDIM + c0) =
                make_float2(acc[mt][nt][2], acc[mt][nt][3]);
        }
    }
}

// ---------------------------------------------------------------------------
extern "C" void kernel_launch(void* const* d_in, const int* in_sizes, int n_in,
                              void* d_out, int out_size) {
    const float* x    = (const float*)d_in[0];
    const float* W    = (const float*)d_in[1];
    const float* bs   = (const float*)d_in[2];
    const float* grid = (const float*)d_in[3];
    float* out = (float*)d_out;

    cudaFuncSetAttribute(kan_gemm, cudaFuncAttributeMaxDynamicSharedMemorySize, SMEM_TOTAL);

    prep<<<NBLK_B + NBLK_A, 256>>>(x, grid, W, bs);
    kan_gemm<<<dim3(OUTDIM / BN, BATCH / BM), 256, SMEM_TOTAL>>>(out);
}

// round 6
// speedup vs baseline: 1.5615x; 1.5615x over previous
#include <cuda_runtime.h>
#include <cuda_fp16.h>
#include <cstdint>
#include <cstddef>

// ---------------------------------------------------------------------------
// FastKAN layer as ONE fp16 GEMM (mma.sync path; tcgen05 unavailable: harness
// compiles PTX at compute_103 which lacks the "a"-suffix features):
//   out[b,j] = sum_{i,s} A[b, i*36+s] * B[j, i*36+s]
//   s in [0,35): cubic B-spline basis coeff c=s;  s==35: silu(x_norm) slot,
//   with B[j, i*36+35] = base_scale[i,j].
// Round 6: revert to R4 structure (single-buffer frags, separate preps);
// keep only the proven B ldmatrix.x4 improvement from R5 (12->8 LDSM per ks).
// ---------------------------------------------------------------------------

#define BATCH   4096
#define INDIM   1024
#define OUTDIM  1024
#define NC      35
#define SLOTS   36
#define KTOT    (INDIM * SLOTS)      // 36864

#define BM      256
#define BN      128
#define BK      64                   // fp16 per K-chunk (128B rows)
#define STAGES  4
#define ITERS   (KTOT / BK)          // 576
#define ATILEB  (BM * BK * 2)        // 32768 bytes
#define BTILEB  (BN * BK * 2)        // 16384 bytes
#define STGB    (ATILEB + BTILEB)    // 49152
#define SMEM_TOTAL (STAGES * STGB)   // 196608

__device__ __align__(128) __half g_A[(size_t)BATCH  * KTOT];  // ~302 MB
__device__ __align__(128) __half g_B[(size_t)OUTDIM * KTOT];  //  ~74 MB

// ------------------------------- helpers -----------------------------------
__device__ __forceinline__ uint32_t smem_u32(const void* p) {
    uint32_t a;
    asm("{ .reg .u64 t; cvta.to.shared.u64 t, %1; cvt.u32.u64 %0, t; }" : "=r"(a) : "l"(p));
    return a;
}
__device__ __forceinline__ void cp16(uint32_t s, const void* g) {
    asm volatile("cp.async.cg.shared.global [%0], [%1], 16;" :: "r"(s), "l"(g) : "memory");
}
#define CP_COMMIT() asm volatile("cp.async.commit_group;" ::: "memory")
#define CP_WAIT(n)  asm volatile("cp.async.wait_group %0;" :: "n"(n) : "memory")
#define SWZ(off) ((off) ^ (((off) >> 3) & 0x70))

// ---------------------------------------------------------------------------
// prep_B: pack spline_weight [i][j][c] + base_scale [i][j] into
//         g_B[j][i*36 + s] fp16 (K-major B operand). 4 j's per thread (MLP).
// ---------------------------------------------------------------------------
__global__ void prep_B(const float* __restrict__ W, const float* __restrict__ bs) {
    int kk = blockIdx.x * 256 + threadIdx.x;   // [0, 36864)
    int j0 = blockIdx.y * 4;
    int i  = kk / SLOTS;
    int s  = kk - i * SLOTS;
    #pragma unroll
    for (int q = 0; q < 4; q++) {
        int j = j0 + q;
        float v = (s < NC) ? W[((size_t)i * OUTDIM + j) * NC + s]
                           : bs[(size_t)i * OUTDIM + j];
        g_B[(size_t)j * KTOT + kk] = __float2half_rn(v);
    }
}

// ---------------------------------------------------------------------------
// prep_A: per (b,i), 4 active cubic B-spline taps + silu slot 35 into
//         g_A[b][i*36 + s] fp16. Staged via SMEM (dynamic tap index without
//         register spills), then coalesced block copy to global.
// ---------------------------------------------------------------------------
__global__ void prep_A(const float* __restrict__ x, const float* __restrict__ grid) {
    __shared__ __half sbuf[256 * SLOTS];
    int tid = threadIdx.x;
    size_t pair0 = (size_t)blockIdx.x * 256;
    float xv = x[pair0 + tid];
    float xn = fminf(fmaxf(xv, -0.99f), 0.99f);

    half2* my2 = (half2*)(sbuf + tid * SLOTS);   // 36 halves = 72B, 4B-aligned
    #pragma unroll
    for (int q = 0; q < SLOTS / 2; q++) my2[q] = __floats2half2_rn(0.f, 0.f);
    __half* my = sbuf + tid * SLOTS;

    const float invh = 17.0f;                     // (NC-1)/2
    float t = (xn + 1.0f) * invh;
    int cl = (int)floorf(t) - 1;                  // active c in [cl, cl+3]
    #pragma unroll
    for (int q = 0; q < 4; q++) {
        int c = cl + q;
        if (c >= 0 && c < NC) {
            float d = fabsf(xn - grid[c]) * invh;
            float inner = 0.66666667f - d * d + d * d * d * 0.5f;
            float tt = 2.0f - d;
            float outer = tt * tt * tt * (1.0f / 6.0f);
            float v = (d < 1.0f) ? inner : ((d < 2.0f) ? outer : 0.0f);
            my[c] = __float2half_rn(v);
        }
    }
    my[NC] = __float2half_rn(xn / (1.0f + __expf(-xn)));
    __syncthreads();

    // 256*36 halves = 4608 u32 words, coalesced copy out
    const uint32_t* s4 = (const uint32_t*)sbuf;
    uint32_t* g4 = (uint32_t*)(g_A + pair0 * SLOTS);
    #pragma unroll
    for (int w = 0; w < 4608 / 256; w++) g4[w * 256 + tid] = s4[w * 256 + tid];
}

// ---------------------------------------------------------------------------
// kan_gemm: 256x128 CTA tile, K=36864, 4-stage cp.async + mma.sync m16n8k16.
// 8 warps as 4(M) x 2(N); warp tile 64x64. One wave: 128 CTAs.
// ---------------------------------------------------------------------------
__global__ void __launch_bounds__(256, 1) kan_gemm(float* __restrict__ out) {
    extern __shared__ __align__(1024) char smem[];
    uint32_t sb = smem_u32(smem);
    int tid = threadIdx.x;
    int wid = tid >> 5;
    int lid = tid & 31;
    int tn  = blockIdx.x;       // [0,8)
    int tm  = blockIdx.y;       // [0,16)
    int wm  = wid & 3;          // 4 warps along M
    int wn  = wid >> 2;         // 2 warps along N

    const __half* gA = g_A + (size_t)(tm * BM) * KTOT;
    const __half* gB = g_B + (size_t)(tn * BN) * KTOT;

    // per-thread copy coordinates: A = 8 chunks of 16B, B = 4 chunks
    int arow[8]; uint32_t acol[8], adst[8];
    #pragma unroll
    for (int q = 0; q < 8; q++) {
        int ci = tid + q * 256;
        arow[q] = ci >> 3;
        acol[q] = (ci & 7) * 8;
        uint32_t off = (uint32_t)arow[q] * 128 + (ci & 7) * 16;
        adst[q] = SWZ(off);
    }
    int brow[4]; uint32_t bcol[4], bdst[4];
    #pragma unroll
    for (int q = 0; q < 4; q++) {
        int ci = tid + q * 256;
        brow[q] = ci >> 3;
        bcol[q] = (ci & 7) * 8;
        uint32_t off = (uint32_t)brow[q] * 128 + (ci & 7) * 16;
        bdst[q] = SWZ(off);
    }

    // fragment base offsets (unswizzled)
    // A tile mt: row = wm*64 + mt*16 + (lid&15); byte col = (lid>>4)*16
    uint32_t afoff[4];
    #pragma unroll
    for (int mt = 0; mt < 4; mt++) {
        uint32_t row = wm * 64 + mt * 16 + (lid & 15);
        afoff[mt] = row * 128 + (lid >> 4) * 16;
    }
    // B pair p covers nt = 2p, 2p+1 via one x4: lane groups of 8 map to
    // (nt0,h0),(nt0,h1),(nt1,h0),(nt1,h1)   [proven correct in round 5]
    uint32_t bfoff[4];
    #pragma unroll
    for (int p = 0; p < 4; p++) {
        int g   = lid >> 3;              // 0..3
        int ntl = 2 * p + (g >> 1);
        int h   = g & 1;
        uint32_t row = wn * 64 + ntl * 8 + (lid & 7);
        bfoff[p] = row * 128 + h * 16;
    }

    float acc[4][8][4];
    #pragma unroll
    for (int a = 0; a < 4; a++)
        #pragma unroll
        for (int b = 0; b < 8; b++)
            #pragma unroll
            for (int c = 0; c < 4; c++) acc[a][b][c] = 0.f;

    auto copy_stage = [&](int it) {
        int s = it & (STAGES - 1);
        uint32_t sa  = sb + s * STGB;
        uint32_t sbm = sa + ATILEB;
        size_t k0 = (size_t)it * BK;
        #pragma unroll
        for (int q = 0; q < 8; q++)
            cp16(sa + adst[q], gA + (size_t)arow[q] * KTOT + k0 + acol[q]);
        #pragma unroll
        for (int q = 0; q < 4; q++)
            cp16(sbm + bdst[q], gB + (size_t)brow[q] * KTOT + k0 + bcol[q]);
        CP_COMMIT();
    };

    copy_stage(0); copy_stage(1); copy_stage(2);

    for (int k = 0; k < ITERS; k++) {
        CP_WAIT(2);
        __syncthreads();
        if (k + 3 < ITERS) copy_stage(k + 3); else CP_COMMIT();

        uint32_t sa  = sb + (k & (STAGES - 1)) * STGB;
        uint32_t sbm = sa + ATILEB;

        #pragma unroll
        for (int ks = 0; ks < 4; ks++) {
            uint32_t kb = (uint32_t)ks * 32;
            uint32_t af[4][4];
            uint32_t bf[4][4];
            #pragma unroll
            for (int mt = 0; mt < 4; mt++) {
                uint32_t off = afoff[mt] + kb;
                uint32_t addr = sa + SWZ(off);
                asm volatile(
                    "ldmatrix.sync.aligned.m8n8.x4.shared.b16 {%0,%1,%2,%3}, [%4];"
                    : "=r"(af[mt][0]), "=r"(af[mt][1]), "=r"(af[mt][2]), "=r"(af[mt][3])
                    : "r"(addr));
            }
            #pragma unroll
            for (int p = 0; p < 4; p++) {
                uint32_t off = bfoff[p] + kb;
                uint32_t addr = sbm + SWZ(off);
                asm volatile(
                    "ldmatrix.sync.aligned.m8n8.x4.shared.b16 {%0,%1,%2,%3}, [%4];"
                    : "=r"(bf[p][0]), "=r"(bf[p][1]), "=r"(bf[p][2]), "=r"(bf[p][3])
                    : "r"(addr));
            }
            #pragma unroll
            for (int mt = 0; mt < 4; mt++)
                #pragma unroll
                for (int p = 0; p < 4; p++) {
                    asm volatile(
                        "mma.sync.aligned.m16n8k16.row.col.f32.f16.f16.f32 "
                        "{%0,%1,%2,%3}, {%4,%5,%6,%7}, {%8,%9}, {%0,%1,%2,%3};"
                        : "+f"(acc[mt][2*p][0]), "+f"(acc[mt][2*p][1]),
                          "+f"(acc[mt][2*p][2]), "+f"(acc[mt][2*p][3])
                        : "r"(af[mt][0]), "r"(af[mt][1]), "r"(af[mt][2]), "r"(af[mt][3]),
                          "r"(bf[p][0]), "r"(bf[p][1]));
                    asm volatile(
                        "mma.sync.aligned.m16n8k16.row.col.f32.f16.f16.f32 "
                        "{%0,%1,%2,%3}, {%4,%5,%6,%7}, {%8,%9}, {%0,%1,%2,%3};"
                        : "+f"(acc[mt][2*p+1][0]), "+f"(acc[mt][2*p+1][1]),
                          "+f"(acc[mt][2*p+1][2]), "+f"(acc[mt][2*p+1][3])
                        : "r"(af[mt][0]), "r"(af[mt][1]), "r"(af[mt][2]), "r"(af[mt][3]),
                          "r"(bf[p][2]), "r"(bf[p][3]));
                }
        }
    }
    CP_WAIT(0);

    // Epilogue: mma accum layout -> gmem
    #pragma unroll
    for (int mt = 0; mt < 4; mt++) {
        int r0 = tm * BM + wm * 64 + mt * 16 + (lid >> 2);
        #pragma unroll
        for (int nt = 0; nt < 8; nt++) {
            int c0 = tn * BN + wn * 64 + nt * 8 + (lid & 3) * 2;
            *(float2*)(out + (size_t)r0 * OUTDIM + c0) =
                make_float2(acc[mt][nt][0], acc[mt][nt][1]);
            *(float2*)(out + (size_t)(r0 + 8) * OUTDIM + c0) =
                make_float2(acc[mt][nt][2], acc[mt][nt][3]);
        }
    }
}

// ---------------------------------------------------------------------------
extern "C" void kernel_launch(void* const* d_in, const int* in_sizes, int n_in,
                              void* d_out, int out_size) {
    const float* x    = (const float*)d_in[0];
    const float* W    = (const float*)d_in[1];
    const float* bs   = (const float*)d_in[2];
    const float* grid = (const float*)d_in[3];
    float* out = (float*)d_out;

    cudaFuncSetAttribute(kan_gemm, cudaFuncAttributeMaxDynamicSharedMemorySize, SMEM_TOTAL);

    prep_B<<<dim3(KTOT / 256, OUTDIM / 4), 256>>>(W, bs);
    prep_A<<<(BATCH * INDIM) / 256, 256>>>(x, grid);
    kan_gemm<<<dim3(OUTDIM / BN, BATCH / BM), 256, SMEM_TOTAL>>>(out);
}

// round 7
// speedup vs baseline: 1.8705x; 1.1979x over previous
#include <cuda_runtime.h>
#include <cuda_fp16.h>
#include <cstdint>
#include <cstddef>

// ---------------------------------------------------------------------------
// FastKAN as ONE 2:4-SPARSE fp16 GEMM (mma.sp::ordered_metadata.m16n8k32).
// Logical K' = 40 slots per i (padded for 2:4 legality):
//   pos 0..17  : even coeffs c=2p       (per sample: 2 adjacent nonzero)
//   pos 18,19  : zero pad
//   pos 20..36 : odd coeffs c=2p+1      (per sample: <=2 adjacent nonzero)
//   pos 37     : silu slot (B holds base_scale)
//   pos 38,39  : zero pad
// Every aligned 4-group has <=2 nonzeros -> valid 2:4. A stored compressed
// (20 halves per i) + 4-bit/group metadata; tensor-op count x0.556 vs dense.
// ---------------------------------------------------------------------------

#define BATCH   4096
#define INDIM   1024
#define OUTDIM  1024
#define NC      35
#define SLOTSP  40
#define KTOTL   (INDIM * SLOTSP)     // 40960 logical K
#define KTOTC   (KTOTL / 2)          // 20480 compressed halves per b
#define NMW     (KTOTL / 16)         // 2560 metadata u16 words per b

#define BM      256
#define BN      128
#define BKL     128                  // logical K per main-loop iter
#define ITERS   (KTOTL / BKL)        // 320
#define STAGES  3
#define A_ST    32768                // 256 rows x 128 B (compressed A)
#define B_ST    16384                // 128 rows x 128 B (one k-half of B)
#define M_ST    4096                 // 128 pairs x 32 B metadata
#define STGB    (A_ST + 2 * B_ST + M_ST)   // 69632
#define SMEM_TOTAL (STAGES * STGB)         // 208896

__device__ __align__(128) __half g_Ac[(size_t)BATCH * KTOTC];        // 168 MB
__device__ __align__(128) __half g_B [(size_t)OUTDIM * KTOTL];       //  80 MB
__device__ __align__(128) unsigned short g_Mp[(size_t)BATCH * NMW];  //  20 MB
// g_Mp paired layout: u16 at ((pair*NMW + w)*2 + hb), pair=(b>>4)*8+(b&7),
// hb=(b>>3)&1  ->  u32 word (pair*NMW + w) = {row b (lo16), row b+8 (hi16)}.

// ------------------------------- helpers -----------------------------------
__device__ __forceinline__ uint32_t smem_u32(const void* p) {
    uint32_t a;
    asm("{ .reg .u64 t; cvta.to.shared.u64 t, %1; cvt.u32.u64 %0, t; }" : "=r"(a) : "l"(p));
    return a;
}
__device__ __forceinline__ void cp16(uint32_t s, const void* g) {
    asm volatile("cp.async.cg.shared.global [%0], [%1], 16;" :: "r"(s), "l"(g) : "memory");
}
#define CP_COMMIT() asm volatile("cp.async.commit_group;" ::: "memory")
#define CP_WAIT(n)  asm volatile("cp.async.wait_group %0;" :: "n"(n) : "memory")
#define SWZ(off) ((off) ^ (((off) >> 3) & 0x70))

__device__ __forceinline__ float tapval(float xn, const float* grid, int c) {
    float d = fabsf(xn - __ldg(grid + c)) * 17.0f;
    float inner = 0.66666667f - d * d + d * d * d * 0.5f;
    float tt = 2.0f - d;
    float outer = tt * tt * tt * (1.0f / 6.0f);
    return (d < 1.0f) ? inner : ((d < 2.0f) ? outer : 0.0f);
}

// ---------------------------------------------------------------------------
// prep_B: dense B operand, K' = 40 slots per i.
// ---------------------------------------------------------------------------
__global__ void prep_B(const float* __restrict__ W, const float* __restrict__ bs) {
    int kk = blockIdx.x * 256 + threadIdx.x;   // [0, 40960)
    int j0 = blockIdx.y * 4;
    int i  = kk / SLOTSP;
    int s  = kk - i * SLOTSP;
    #pragma unroll
    for (int q = 0; q < 4; q++) {
        int j = j0 + q;
        float v = 0.0f;
        if (s < 18)                  v = W[((size_t)i * OUTDIM + j) * NC + 2 * s];
        else if (s >= 20 && s <= 36) v = W[((size_t)i * OUTDIM + j) * NC + 2 * (s - 20) + 1];
        else if (s == 37)            v = bs[(size_t)i * OUTDIM + j];
        g_B[(size_t)j * KTOTL + kk] = __float2half_rn(v);
    }
}

// ---------------------------------------------------------------------------
// prep_A: compressed A (2 stored per 4-group) + ordered 2-bit metadata.
// One thread handles 2 i's (so metadata lands on u16 boundaries: 5 u16).
// ---------------------------------------------------------------------------
__global__ void prep_A(const float* __restrict__ x, const float* __restrict__ grid) {
    __shared__ __half sbuf[256 * 40];
    int tid  = threadIdx.x;
    int b    = blockIdx.x >> 1;
    int half = blockIdx.x & 1;
    int i0   = half * 512 + 2 * tid;

    unsigned long long mbits[2];
    #pragma unroll
    for (int w = 0; w < 2; w++) {
        int i = i0 + w;
        float xv = x[(size_t)b * INDIM + i];
        float xn = fminf(fmaxf(xv, -0.99f), 0.99f);
        float t  = (xn + 1.0f) * 17.0f;
        int cl = (int)floorf(t) - 1;
        int a  = cl > 0 ? cl : 0;
        int ub = cl + 3 < 34 ? cl + 3 : 34;
        int ce0 = a + (a & 1);           // two even taps, always valid
        int ce1 = ce0 + 2;
        int o0  = a + 1 - (a & 1);       // first odd tap, always valid
        int o1  = o0 + 2;
        bool ho1 = (o1 <= ub);

        int   cp[5]; float cv[5]; bool cok[5];
        cp[0] = ce0 >> 1;             cv[0] = tapval(xn, grid, ce0);          cok[0] = true;
        cp[1] = ce1 >> 1;             cv[1] = tapval(xn, grid, ce1);          cok[1] = true;
        cp[2] = 20 + ((o0 - 1) >> 1); cv[2] = tapval(xn, grid, o0);           cok[2] = true;
        cp[3] = 20 + ((o1 - 1) >> 1); cv[3] = tapval(xn, grid, ho1 ? o1 : 34); cok[3] = ho1;
        cp[4] = 37;                   cv[4] = xn / (1.0f + __expf(-xn));      cok[4] = true;

        unsigned long long m = 0;
        #pragma unroll
        for (int u = 0; u < 10; u++) {
            int e0 = -1, e1 = -1; float v0 = 0.f, v1 = 0.f;
            #pragma unroll
            for (int q = 0; q < 5; q++) {
                if (cok[q] && (cp[q] >> 2) == u) {
                    if (e0 < 0) { e0 = cp[q] & 3; v0 = cv[q]; }
                    else        { e1 = cp[q] & 3; v1 = cv[q]; }
                }
            }
            if (e0 < 0) { e0 = 0; e1 = 1; }
            else if (e1 < 0) {
                if (e0 == 3) { e1 = 3; v1 = v0; e0 = 2; v0 = 0.f; }
                else         { e1 = 3; }
            }
            sbuf[tid * 40 + w * 20 + 2 * u]     = __float2half_rn(v0);
            sbuf[tid * 40 + w * 20 + 2 * u + 1] = __float2half_rn(v1);
            m |= (unsigned long long)(e0 | (e1 << 2)) << (4 * u);
        }
        mbits[w] = m;
    }

    // pack 2x40 metadata bits into 5 u16, store into paired layout
    {
        unsigned long long m0 = mbits[0], m1 = mbits[1];
        unsigned short ws[5];
        ws[0] = (unsigned short)(m0);
        ws[1] = (unsigned short)(m0 >> 16);
        ws[2] = (unsigned short)(((m0 >> 32) & 0xFFull) | ((m1 & 0xFFull) << 8));
        ws[3] = (unsigned short)(m1 >> 8);
        ws[4] = (unsigned short)(m1 >> 24);
        int pairidx = (b >> 4) * 8 + (b & 7);
        int hb = (b >> 3) & 1;
        unsigned short* mp = g_Mp + ((size_t)pairidx * NMW + half * 1280 + 5 * tid) * 2 + hb;
        #pragma unroll
        for (int q = 0; q < 5; q++) mp[2 * q] = ws[q];
    }

    __syncthreads();
    const uint32_t* s4 = (const uint32_t*)sbuf;
    uint32_t* g4 = (uint32_t*)(g_Ac + ((size_t)b * KTOTC + half * 10240));
    #pragma unroll
    for (int q = 0; q < 20; q++) g4[q * 256 + tid] = s4[q * 256 + tid];
}

// ---------------------------------------------------------------------------
// kan_gemm: 256x128 tile, 3-stage cp.async + mma.sp::ordered_metadata
// m16n8k32. 8 warps 4(M)x2(N), warp tile 64x64. 128 CTAs = one wave.
// ---------------------------------------------------------------------------
__global__ void __launch_bounds__(256, 1) kan_gemm(float* __restrict__ out) {
    extern __shared__ __align__(1024) char smem[];
    uint32_t sb0 = smem_u32(smem);
    int tid = threadIdx.x;
    int wid = tid >> 5;
    int lid = tid & 31;
    int tn  = blockIdx.x;       // [0,8)
    int tm  = blockIdx.y;       // [0,16)
    int wm  = wid & 3;
    int wn  = wid >> 2;

    const __half* gA = g_Ac + (size_t)(tm * BM) * KTOTC;
    const __half* gB = g_B + (size_t)(tn * BN) * KTOTL;
    const uint32_t* gM = ((const uint32_t*)g_Mp) + (size_t)(tm * 128) * NMW;

    // copy coords: A 8 chunks (256 rows x 128B), B 4 chunks per half (128x128B)
    int arow[8]; uint32_t acol[8], adst[8];
    #pragma unroll
    for (int q = 0; q < 8; q++) {
        int ci = tid + q * 256;
        arow[q] = ci >> 3; acol[q] = (ci & 7) * 8;
        adst[q] = SWZ((uint32_t)arow[q] * 128 + (ci & 7) * 16);
    }
    int brow[4]; uint32_t bcol[4], bdst[4];
    #pragma unroll
    for (int q = 0; q < 4; q++) {
        int ci = tid + q * 256;
        brow[q] = ci >> 3; bcol[q] = (ci & 7) * 8;
        bdst[q] = SWZ((uint32_t)brow[q] * 128 + (ci & 7) * 16);
    }
    int mpp  = tid >> 1;                    // pair row [0,128)
    int mhh  = tid & 1;                     // source k-half
    uint32_t mdst = (uint32_t)mpp * 32 + (uint32_t)((mhh ^ ((mpp >> 2) & 1)) * 16);

    // fragment bases (unswizzled)
    uint32_t afb = (uint32_t)(wm * 64 + (lid & 15)) * 128 + (lid >> 4) * 16;
    uint32_t bfb = (uint32_t)(wn * 64 + (lid & 7)) * 128 + (lid >> 3) * 16;
    int qg = lid >> 2;          // quad -> rows qg, qg+8 of 16-row tile
    int c2 = lid & 1;           // metadata k-half this lane supplies

    float acc[4][8][4];
    #pragma unroll
    for (int a = 0; a < 4; a++)
        #pragma unroll
        for (int b = 0; b < 8; b++)
            #pragma unroll
            for (int c = 0; c < 4; c++) acc[a][b][c] = 0.f;

    auto copy_stage = [&](int it) {
        int s = it % 3;
        uint32_t sa  = sb0 + s * STGB;
        uint32_t sB0 = sa + A_ST, sB1 = sB0 + B_ST, sM = sB1 + B_ST;
        int k64 = it * 64;      // compressed halves
        int kL  = it * 128;     // logical halves (B)
        #pragma unroll
        for (int q = 0; q < 8; q++)
            cp16(sa + adst[q], gA + (size_t)arow[q] * KTOTC + k64 + acol[q]);
        #pragma unroll
        for (int q = 0; q < 4; q++)
            cp16(sB0 + bdst[q], gB + (size_t)brow[q] * KTOTL + kL + bcol[q]);
        #pragma unroll
        for (int q = 0; q < 4; q++)
            cp16(sB1 + bdst[q], gB + (size_t)brow[q] * KTOTL + kL + 64 + bcol[q]);
        cp16(sM + mdst, (const char*)(gM + (size_t)mpp * NMW + it * 8 + mhh * 4));
        CP_COMMIT();
    };

    copy_stage(0); copy_stage(1);

    for (int k = 0; k < ITERS; k++) {
        CP_WAIT(1);
        __syncthreads();
        if (k + 2 < ITERS) copy_stage(k + 2); else CP_COMMIT();

        int s = k % 3;
        uint32_t sa  = sb0 + s * STGB;
        uint32_t sB0 = sa + A_ST, sB1 = sB0 + B_ST, sM = sB1 + B_ST;

        #pragma unroll
        for (int ks = 0; ks < 4; ks++) {
            uint32_t af[4][4];
            uint32_t em[4];
            #pragma unroll
            for (int mt = 0; mt < 4; mt++) {
                uint32_t addr = sa + SWZ(afb + mt * 2048 + ks * 32);
                asm volatile(
                    "ldmatrix.sync.aligned.m8n8.x4.shared.b16 {%0,%1,%2,%3}, [%4];"
                    : "=r"(af[mt][0]), "=r"(af[mt][1]), "=r"(af[mt][2]), "=r"(af[mt][3])
                    : "r"(addr));
            }
            #pragma unroll
            for (int mt = 0; mt < 4; mt++) {
                uint32_t pr = (uint32_t)((wm * 4 + mt) * 8 + qg);
                uint32_t moff = sM + pr * 32 + ((uint32_t)((ks * 2 + c2) * 4) ^ ((pr & 4) << 2));
                asm volatile("ld.shared.b32 %0, [%1];" : "=r"(em[mt]) : "r"(moff));
            }
            uint32_t bh = (ks < 2) ? sB0 : sB1;
            uint32_t kb = (uint32_t)(ks & 1) * 64;
            #pragma unroll
            for (int nh = 0; nh < 2; nh++) {
                uint32_t bf[4][4];
                #pragma unroll
                for (int j = 0; j < 4; j++) {
                    int nt = nh * 4 + j;
                    uint32_t addr = bh + SWZ(bfb + nt * 1024 + kb);
                    asm volatile(
                        "ldmatrix.sync.aligned.m8n8.x4.shared.b16 {%0,%1,%2,%3}, [%4];"
                        : "=r"(bf[j][0]), "=r"(bf[j][1]), "=r"(bf[j][2]), "=r"(bf[j][3])
                        : "r"(addr));
                }
                #pragma unroll
                for (int mt = 0; mt < 4; mt++)
                    #pragma unroll
                    for (int j = 0; j < 4; j++) {
                        asm volatile(
                            "mma.sp::ordered_metadata.sync.aligned.m16n8k32.row.col.f32.f16.f16.f32 "
                            "{%0,%1,%2,%3}, {%4,%5,%6,%7}, {%8,%9,%10,%11}, {%0,%1,%2,%3}, %12, 0x0;"
                            : "+f"(acc[mt][nh * 4 + j][0]), "+f"(acc[mt][nh * 4 + j][1]),
                              "+f"(acc[mt][nh * 4 + j][2]), "+f"(acc[mt][nh * 4 + j][3])
                            : "r"(af[mt][0]), "r"(af[mt][1]), "r"(af[mt][2]), "r"(af[mt][3]),
                              "r"(bf[j][0]), "r"(bf[j][1]), "r"(bf[j][2]), "r"(bf[j][3]),
                              "r"(em[mt]));
                    }
            }
        }
    }
    CP_WAIT(0);

    // Epilogue
    #pragma unroll
    for (int mt = 0; mt < 4; mt++) {
        int r0 = tm * BM + wm * 64 + mt * 16 + (lid >> 2);
        #pragma unroll
        for (int nt = 0; nt < 8; nt++) {
            int c0 = tn * BN + wn * 64 + nt * 8 + (lid & 3) * 2;
            *(float2*)(out + (size_t)r0 * OUTDIM + c0) =
                make_float2(acc[mt][nt][0], acc[mt][nt][1]);
            *(float2*)(out + (size_t)(r0 + 8) * OUTDIM + c0) =
                make_float2(acc[mt][nt][2], acc[mt][nt][3]);
        }
    }
}

// ---------------------------------------------------------------------------
extern "C" void kernel_launch(void* const* d_in, const int* in_sizes, int n_in,
                              void* d_out, int out_size) {
    const float* x    = (const float*)d_in[0];
    const float* W    = (const float*)d_in[1];
    const float* bs   = (const float*)d_in[2];
    const float* grid = (const float*)d_in[3];
    float* out = (float*)d_out;

    cudaFuncSetAttribute(kan_gemm, cudaFuncAttributeMaxDynamicSharedMemorySize, SMEM_TOTAL);

    prep_B<<<dim3(KTOTL / 256, OUTDIM / 4), 256>>>(W, bs);
    prep_A<<<BATCH * 2, 256>>>(x, grid);
    kan_gemm<<<dim3(OUTDIM / BN, BATCH / BM), 256, SMEM_TOTAL>>>(out);
}